// round 3
// baseline (speedup 1.0000x reference)
#include <cuda_runtime.h>

#define T_STEPS 2048
#define BATCH   256
#define HID     64
#define NG      256
#define NOUT    11

typedef unsigned long long u64;

// Scratch: h sequence (reused across layers), x-projection, final h.
__device__ float g_hbuf[(size_t)BATCH * T_STEPS * HID];   // 128 MB
__device__ float g_xp[(size_t)BATCH * T_STEPS * NG];      // 512 MB
__device__ float g_hfin[BATCH * HID];

__device__ __forceinline__ u64 pack2(float a, float b) {
    u64 r; asm("mov.b64 %0, {%1,%2};" : "=l"(r) : "f"(a), "f"(b)); return r;
}
__device__ __forceinline__ void unpack2(u64 v, float& a, float& b) {
    asm("mov.b64 {%0,%1}, %2;" : "=f"(a), "=f"(b) : "l"(v));
}
__device__ __forceinline__ void ffma2(u64& d, u64 a, u64 b) {
    asm("fma.rn.f32x2 %0, %1, %2, %0;" : "+l"(d) : "l"(a), "l"(b));
}
__device__ __forceinline__ float sigf(float x) {
    return __fdividef(1.0f, 1.0f + __expf(-x));
}
__device__ __forceinline__ float tanh2(float x) { return 2.0f * sigf(2.0f * x) - 1.0f; }

// ---------------------------------------------------------------------------
// Bulk x-projection GEMM: g_xp[m][g] = sum_k W_ih[g][k] * g_hbuf[m][k] + bias[g]
// m = batch*T + t (524288 rows), g = gate row (256), K = 64.
// Thread = gate row g, weights in registers; 128-row h tile in smem.
// ---------------------------------------------------------------------------
__global__ __launch_bounds__(256, 1)
void xproj_gemm(const float* __restrict__ W_ih,
                const float* __restrict__ b_ih,
                const float* __restrict__ b_hh)
{
    __shared__ __align__(16) float sh[128 * HID];
    const int tid = threadIdx.x;
    const size_t m0 = (size_t)blockIdx.x * 128;

    // cooperative tile load (32 KB, coalesced float4)
    const float4* src = (const float4*)(g_hbuf + m0 * HID);
    float4* dst = (float4*)sh;
#pragma unroll
    for (int i = 0; i < 8; i++) dst[tid + i * 256] = src[tid + i * 256];

    u64 w[32];
    const float4* wr = (const float4*)(W_ih + tid * HID);
#pragma unroll
    for (int i = 0; i < 16; i++) {
        float4 v = wr[i];
        w[2 * i] = pack2(v.x, v.y); w[2 * i + 1] = pack2(v.z, v.w);
    }
    const float bias = b_ih[tid] + b_hh[tid];
    __syncthreads();

    float* out = g_xp + m0 * NG + tid;
#pragma unroll 2
    for (int m = 0; m < 128; m++) {
        const ulonglong2* hr = (const ulonglong2*)(sh + m * HID);
        u64 a0 = 0, a1 = 0, a2 = 0, a3 = 0;
#pragma unroll
        for (int k = 0; k < 8; k++) {
            ulonglong2 p = hr[2 * k], q = hr[2 * k + 1];   // broadcast LDS.128
            ffma2(a0, p.x, w[4 * k]);     ffma2(a1, p.y, w[4 * k + 1]);
            ffma2(a2, q.x, w[4 * k + 2]); ffma2(a3, q.y, w[4 * k + 3]);
        }
        float x0, x1, x2, x3, x4, x5, x6, x7;
        unpack2(a0, x0, x1); unpack2(a1, x2, x3);
        unpack2(a2, x4, x5); unpack2(a3, x6, x7);
        out[(size_t)m * NG] = bias + ((x0 + x1) + (x2 + x3)) + ((x4 + x5) + (x6 + x7));
    }
}

// ---------------------------------------------------------------------------
// Recurrent kernel. CTA = 2 batch elems, 256 threads.
// tid -> be = tid>>7, r = tid&127, j = r>>1, role = r&1 (lane pairs).
//   role 0 owns gate rows (j, 128+j)   = (i, g)
//   role 1 owns gate rows (64+j,192+j) = (f, o)
// Gates stay in registers; sig(i)*tanh(g) crosses via shfl.xor(1).
// One barrier per step; sh double-buffered.
// MODE 0: x input (K=2, bias in-kernel), writes g_hbuf.
// MODE 1: g_xp input (bias folded),      writes g_hbuf.
// MODE 2: g_xp input, writes g_hfin at t = T-1.
// ---------------------------------------------------------------------------
template<int MODE>
__global__ __launch_bounds__(256, 1)
void lstm_rec(const float* __restrict__ x_in,
              const float* __restrict__ W_hh,
              const float* __restrict__ W_ih,
              const float* __restrict__ b_ih,
              const float* __restrict__ b_hh)
{
    __shared__ __align__(16) float sh[2][2][HID];  // [buf][be][j]
    __shared__ float sx[2][2][2];                  // MODE 0: [buf][be][feat]

    const int tid  = threadIdx.x;
    const int be   = tid >> 7;
    const int r    = tid & 127;
    const int j    = r >> 1;
    const int role = r & 1;
    const int bg   = blockIdx.x * 2 + be;

    const int rowA = role ? (64 + j) : j;
    const int rowB = rowA + 128;

    u64 wA[32], wB[32];
    {
        const float4* pa = (const float4*)(W_hh + rowA * HID);
        const float4* pb = (const float4*)(W_hh + rowB * HID);
#pragma unroll
        for (int i = 0; i < 16; i++) {
            float4 va = pa[i], vb = pb[i];
            wA[2 * i] = pack2(va.x, va.y); wA[2 * i + 1] = pack2(va.z, va.w);
            wB[2 * i] = pack2(vb.x, vb.y); wB[2 * i + 1] = pack2(vb.z, vb.w);
        }
    }

    float biasA = 0.f, biasB = 0.f, wxA0 = 0.f, wxA1 = 0.f, wxB0 = 0.f, wxB1 = 0.f;
    if (MODE == 0) {
        biasA = b_ih[rowA] + b_hh[rowA];
        biasB = b_ih[rowB] + b_hh[rowB];
        wxA0 = W_ih[rowA * 2]; wxA1 = W_ih[rowA * 2 + 1];
        wxB0 = W_ih[rowB * 2]; wxB1 = W_ih[rowB * 2 + 1];
    }

    // init h_{-1} = 0
    if (role) sh[0][be][j] = 0.f;

    // MODE 0: stage x_0, hold x_1
    float xn0 = 0.f, xn1 = 0.f;
    if (MODE == 0 && r == 0) {
        const float2* xq = (const float2*)(x_in + (size_t)bg * T_STEPS * 2);
        float2 x0 = xq[0]; sx[0][be][0] = x0.x; sx[0][be][1] = x0.y;
        float2 x1 = xq[1]; xn0 = x1.x; xn1 = x1.y;
    }

    // MODE>=1: distance-2 xp prefetch
    const float* xpb = g_xp + (size_t)bg * T_STEPS * NG;
    float xpA0 = 0.f, xpB0 = 0.f, xpA1 = 0.f, xpB1 = 0.f;
    if (MODE >= 1) {
        xpA0 = xpb[rowA];      xpB0 = xpb[rowB];
        xpA1 = xpb[NG + rowA]; xpB1 = xpb[NG + rowB];
    }

    float c = 0.f;
    float* hb = g_hbuf + (size_t)bg * T_STEPS * HID;
    __syncthreads();

    for (int t = 0; t < T_STEPS; t++) {
        const int p = t & 1;
        // --- h-matmul: 2 gate rows, shared LDS of h ---
        const ulonglong2* hr = (const ulonglong2*)sh[p][be];
        u64 aA0 = 0, aA1 = 0, aB0 = 0, aB1 = 0;
#pragma unroll
        for (int k = 0; k < 16; k++) {
            ulonglong2 pv = hr[k];                     // broadcast LDS.128
            ffma2(aA0, pv.x, wA[2 * k]); ffma2(aA1, pv.y, wA[2 * k + 1]);
            ffma2(aB0, pv.x, wB[2 * k]); ffma2(aB1, pv.y, wB[2 * k + 1]);
        }
        float zA, zB;
        {
            float u0, u1, u2, u3;
            unpack2(aA0, u0, u1); unpack2(aA1, u2, u3); zA = (u0 + u1) + (u2 + u3);
            unpack2(aB0, u0, u1); unpack2(aB1, u2, u3); zB = (u0 + u1) + (u2 + u3);
        }
        if (MODE == 0) {
            float xv0 = sx[p][be][0], xv1 = sx[p][be][1];
            zA += biasA + wxA0 * xv0 + wxA1 * xv1;
            zB += biasB + wxB0 * xv0 + wxB1 * xv1;
        } else {
            zA += xpA0; zB += xpB0;
        }
        // --- prefetch xp for t+2 (consumed after ~2 steps > DRAM latency) ---
        if (MODE >= 1) {
            xpA0 = xpA1; xpB0 = xpB1;
            int tn = (t + 2 < T_STEPS) ? (t + 2) : (T_STEPS - 1);
            xpA1 = xpb[(size_t)tn * NG + rowA];
            xpB1 = xpb[(size_t)tn * NG + rowB];
        }
        // --- pointwise, warp-local via shfl pair ---
        float sA = sigf(zA);               // role0: sig(i), role1: sig(f)
        float a  = sA * tanh2(zB);         // role0: i*tanh(g)
        float ar = __shfl_xor_sync(0xffffffffu, a, 1);
        if (role) {
            c = sA * c + ar;
            float h = sigf(zB) * tanh2(c);
            sh[p ^ 1][be][j] = h;
            if (MODE <= 1) hb[(size_t)t * HID + j] = h;
            if (MODE == 2 && t == T_STEPS - 1) g_hfin[bg * HID + j] = h;
        }
        if (MODE == 0 && r == 0) {
            sx[p ^ 1][be][0] = xn0; sx[p ^ 1][be][1] = xn1;
            int tn = (t + 2 < T_STEPS) ? (t + 2) : (T_STEPS - 1);
            const float2* xq = (const float2*)(x_in + (size_t)bg * T_STEPS * 2);
            float2 xv = xq[tn]; xn0 = xv.x; xn1 = xv.y;
        }
        __syncthreads();
    }
}

__global__ void final_linear_kernel(const float* __restrict__ W_out,
                                    const float* __restrict__ b_out,
                                    float* __restrict__ out)
{
    int idx = blockIdx.x * blockDim.x + threadIdx.x;
    if (idx >= BATCH * NOUT) return;
    int b = idx / NOUT, o = idx - b * NOUT;
    float s = b_out[o];
    const float* h  = &g_hfin[b * HID];
    const float* wr = &W_out[o * HID];
#pragma unroll 16
    for (int k = 0; k < HID; k++) s += h[k] * wr[k];
    out[idx] = s;
}

extern "C" void kernel_launch(void* const* d_in, const int* in_sizes, int n_in,
                              void* d_out, int out_size)
{
    const float* x    = (const float*)d_in[0];
    const float* Wih0 = (const float*)d_in[1];
    const float* Whh0 = (const float*)d_in[2];
    const float* bih0 = (const float*)d_in[3];
    const float* bhh0 = (const float*)d_in[4];
    const float* Wih1 = (const float*)d_in[5];
    const float* Whh1 = (const float*)d_in[6];
    const float* bih1 = (const float*)d_in[7];
    const float* bhh1 = (const float*)d_in[8];
    const float* Wih2 = (const float*)d_in[9];
    const float* Whh2 = (const float*)d_in[10];
    const float* bih2 = (const float*)d_in[11];
    const float* bhh2 = (const float*)d_in[12];
    const float* Wout = (const float*)d_in[13];
    const float* bout = (const float*)d_in[14];

    dim3 rgrid(BATCH / 2), rblock(256);
    dim3 ggrid(BATCH * T_STEPS / 128), gblock(256);

    lstm_rec<0><<<rgrid, rblock>>>(x, Whh0, Wih0, bih0, bhh0);          // -> g_hbuf
    xproj_gemm<<<ggrid, gblock>>>(Wih1, bih1, bhh1);                    // g_hbuf -> g_xp
    lstm_rec<1><<<rgrid, rblock>>>(nullptr, Whh1, nullptr, nullptr, nullptr);  // -> g_hbuf
    xproj_gemm<<<ggrid, gblock>>>(Wih2, bih2, bhh2);                    // g_hbuf -> g_xp
    lstm_rec<2><<<rgrid, rblock>>>(nullptr, Whh2, nullptr, nullptr, nullptr);  // -> g_hfin
    final_linear_kernel<<<(BATCH * NOUT + 255) / 256, 256>>>(Wout, bout, (float*)d_out);
}